// round 1
// baseline (speedup 1.0000x reference)
#include <cuda_runtime.h>
#include <cuda_bf16.h>
#include <math.h>

// Problem constants (fixed by the reference)
#define BB 2
#define SS 2048
#define DD 1024
#define HH 16
#define KHH 4
#define DKK 64
#define REP 4

// Scratch (device globals; no allocation allowed)
__device__ float g_q[BB * SS * HH * DKK];    // (b,s,h,dk)  4096x1024
__device__ float g_k[BB * SS * KHH * DKK];   // (b,s,kh,dk) 4096x256
__device__ float g_v[BB * SS * KHH * DKK];   // (b,s,kh,dk) 4096x256
__device__ float g_o[BB * SS * HH * DKK];    // attention out, (b,s,h,dk)

// ---------------------------------------------------------------------------
// SGEMM: C[M,N] = A[M,K] @ B[K,N] + bias[N]
// BM=BN=128, BK=8, 256 threads, 8x8 per-thread micro-tile.
// Requires M%128==0, N%128==0, K%8==0 (true for all our shapes).
// ---------------------------------------------------------------------------
__global__ __launch_bounds__(256, 2)
void sgemm_bias_kernel(const float* __restrict__ A, const float* __restrict__ Bm,
                       const float* __restrict__ bias, float* __restrict__ C,
                       int M, int N, int K) {
    __shared__ float As[8][128];
    __shared__ float Bs[8][128];

    const int tid = threadIdx.x;
    const int m0 = blockIdx.y * 128;
    const int n0 = blockIdx.x * 128;
    const int ty = tid / 16;      // 0..15 -> rows ty*8..ty*8+7
    const int tx = tid % 16;      // 0..15 -> cols tx*8..tx*8+7

    const int a_row = tid >> 1;          // 0..127
    const int a_col = (tid & 1) * 4;     // 0 or 4
    const int b_row = tid >> 5;          // 0..7
    const int b_col = (tid & 31) * 4;    // 0..124

    float acc[8][8];
#pragma unroll
    for (int i = 0; i < 8; i++)
#pragma unroll
        for (int j = 0; j < 8; j++) acc[i][j] = 0.0f;

    for (int k0 = 0; k0 < K; k0 += 8) {
        float4 av = *reinterpret_cast<const float4*>(&A[(m0 + a_row) * K + k0 + a_col]);
        As[a_col + 0][a_row] = av.x;
        As[a_col + 1][a_row] = av.y;
        As[a_col + 2][a_row] = av.z;
        As[a_col + 3][a_row] = av.w;
        *reinterpret_cast<float4*>(&Bs[b_row][b_col]) =
            *reinterpret_cast<const float4*>(&Bm[(k0 + b_row) * N + n0 + b_col]);
        __syncthreads();

#pragma unroll
        for (int kk = 0; kk < 8; kk++) {
            float a[8], b[8];
            *reinterpret_cast<float4*>(a)     = *reinterpret_cast<float4*>(&As[kk][ty * 8]);
            *reinterpret_cast<float4*>(a + 4) = *reinterpret_cast<float4*>(&As[kk][ty * 8 + 4]);
            *reinterpret_cast<float4*>(b)     = *reinterpret_cast<float4*>(&Bs[kk][tx * 8]);
            *reinterpret_cast<float4*>(b + 4) = *reinterpret_cast<float4*>(&Bs[kk][tx * 8 + 4]);
#pragma unroll
            for (int i = 0; i < 8; i++)
#pragma unroll
                for (int j = 0; j < 8; j++) acc[i][j] = fmaf(a[i], b[j], acc[i][j]);
        }
        __syncthreads();
    }

#pragma unroll
    for (int i = 0; i < 8; i++) {
        int row = m0 + ty * 8 + i;
#pragma unroll
        for (int j = 0; j < 8; j++) {
            int col = n0 + tx * 8 + j;
            C[row * N + col] = acc[i][j] + bias[col];
        }
    }
}

// ---------------------------------------------------------------------------
// RoPE, in-place on g_q and g_k. One thread per (row, d) pair with d < 32.
// Angle computed in double to sit within fp32-reference tolerance.
// ---------------------------------------------------------------------------
__global__ void rope_kernel(float* __restrict__ q, float* __restrict__ k) {
    const int NQ = BB * SS * HH * 32;
    const int NK = BB * SS * KHH * 32;
    int idx = blockIdx.x * blockDim.x + threadIdx.x;
    if (idx >= NQ + NK) return;

    float* p;
    int s, d;
    if (idx < NQ) {
        int row = idx >> 5;
        d = idx & 31;
        p = q + (size_t)row * DKK;
        s = (row / HH) % SS;
    } else {
        int i2 = idx - NQ;
        int row = i2 >> 5;
        d = i2 & 31;
        p = k + (size_t)row * DKK;
        s = (row / KHH) % SS;
    }

    double theta = pow(10000.0, -(double)d / 32.0);
    double f = (double)s * theta;
    float c = (float)cos(f);
    float sn = (float)sin(f);
    float x1 = p[d];
    float x2 = p[d + 32];
    p[d] = x1 * c - x2 * sn;
    p[d + 32] = x2 * c + x1 * sn;
}

// ---------------------------------------------------------------------------
// Flash attention (causal, GQA). One block per (q_tile=64 rows, h, b).
// 256 threads. S-tile and O-tile computed as 4x4 per-thread micro-tiles.
// Online softmax with running m/l per row. Output in (b,s,h,dk) layout.
// ---------------------------------------------------------------------------
#define FLASH_SMEM_FLOATS (4 * 64 * 65 + 3 * 64)

__global__ __launch_bounds__(256, 2)
void flash_kernel(const float* __restrict__ q, const float* __restrict__ k,
                  const float* __restrict__ v, float* __restrict__ o) {
    extern __shared__ float sm[];
    float* Qs = sm;                 // 64 x 65
    float* Ks = sm + 4160;          // 64 x 65
    float* Vs = sm + 8320;          // 64 x 65
    float* Ss = sm + 12480;         // 64 x 65
    float* m_sh = sm + 16640;       // 64
    float* l_sh = m_sh + 64;        // 64
    float* al_sh = l_sh + 64;       // 64

    const int tid = threadIdx.x;
    const int qt = blockIdx.x;
    const int h = blockIdx.y;
    const int b = blockIdx.z;
    const int kh = h >> 2;          // h / REP
    const int s0q = qt * 64;

    // Load Q tile (rows = q positions, cols = dk)
    for (int t = tid; t < 64 * 16; t += 256) {
        int r = t >> 4;
        int d = (t & 15) * 4;
        float4 val = *reinterpret_cast<const float4*>(
            &q[(((size_t)(b * SS + s0q + r)) * HH + h) * DKK + d]);
        Qs[r * 65 + d + 0] = val.x;
        Qs[r * 65 + d + 1] = val.y;
        Qs[r * 65 + d + 2] = val.z;
        Qs[r * 65 + d + 3] = val.w;
    }
    if (tid < 64) { m_sh[tid] = -1e30f; l_sh[tid] = 0.0f; }

    const int ty = tid / 16;
    const int tx = tid % 16;
    float oacc[4][4];
#pragma unroll
    for (int i = 0; i < 4; i++)
#pragma unroll
        for (int j = 0; j < 4; j++) oacc[i][j] = 0.0f;

    for (int kt = 0; kt <= qt; kt++) {
        const int s0k = kt * 64;
        __syncthreads();  // prev PV done (and Q/m/l ready on first iter)

        // Load K and V tiles
        for (int t = tid; t < 64 * 16; t += 256) {
            int r = t >> 4;
            int d = (t & 15) * 4;
            size_t base = (((size_t)(b * SS + s0k + r)) * KHH + kh) * DKK + d;
            float4 kv = *reinterpret_cast<const float4*>(&k[base]);
            Ks[r * 65 + d + 0] = kv.x;
            Ks[r * 65 + d + 1] = kv.y;
            Ks[r * 65 + d + 2] = kv.z;
            Ks[r * 65 + d + 3] = kv.w;
            float4 vv = *reinterpret_cast<const float4*>(&v[base]);
            Vs[r * 65 + d + 0] = vv.x;
            Vs[r * 65 + d + 1] = vv.y;
            Vs[r * 65 + d + 2] = vv.z;
            Vs[r * 65 + d + 3] = vv.w;
        }
        __syncthreads();

        // S = scale * Q @ K^T, causal mask, write to Ss
        float sacc[4][4];
#pragma unroll
        for (int i = 0; i < 4; i++)
#pragma unroll
            for (int j = 0; j < 4; j++) sacc[i][j] = 0.0f;

#pragma unroll 8
        for (int kk = 0; kk < 64; kk++) {
            float qa[4], kb[4];
#pragma unroll
            for (int i = 0; i < 4; i++) qa[i] = Qs[(ty * 4 + i) * 65 + kk];
#pragma unroll
            for (int j = 0; j < 4; j++) kb[j] = Ks[(tx * 4 + j) * 65 + kk];
#pragma unroll
            for (int i = 0; i < 4; i++)
#pragma unroll
                for (int j = 0; j < 4; j++) sacc[i][j] = fmaf(qa[i], kb[j], sacc[i][j]);
        }
#pragma unroll
        for (int i = 0; i < 4; i++) {
            int r = ty * 4 + i;
#pragma unroll
            for (int j = 0; j < 4; j++) {
                int c = tx * 4 + j;
                float val = sacc[i][j] * 0.125f;
                if (s0k + c > s0q + r) val = -1e30f;
                Ss[r * 65 + c] = val;
            }
        }
        __syncthreads();

        // Online softmax: one thread per row
        if (tid < 64) {
            int r = tid;
            float mo = m_sh[r];
            float mx = mo;
#pragma unroll 8
            for (int c = 0; c < 64; c++) mx = fmaxf(mx, Ss[r * 65 + c]);
            float al = __expf(mo - mx);
            float sum = 0.0f;
#pragma unroll 8
            for (int c = 0; c < 64; c++) {
                float p = __expf(Ss[r * 65 + c] - mx);
                Ss[r * 65 + c] = p;
                sum += p;
            }
            l_sh[r] = l_sh[r] * al + sum;
            m_sh[r] = mx;
            al_sh[r] = al;
        }
        __syncthreads();

        // O = O * alpha + P @ V
        float al[4];
#pragma unroll
        for (int i = 0; i < 4; i++) al[i] = al_sh[ty * 4 + i];
#pragma unroll
        for (int i = 0; i < 4; i++)
#pragma unroll
            for (int j = 0; j < 4; j++) oacc[i][j] *= al[i];

#pragma unroll 8
        for (int kk = 0; kk < 64; kk++) {
            float pa[4], vb[4];
#pragma unroll
            for (int i = 0; i < 4; i++) pa[i] = Ss[(ty * 4 + i) * 65 + kk];
#pragma unroll
            for (int j = 0; j < 4; j++) vb[j] = Vs[kk * 65 + tx * 4 + j];
#pragma unroll
            for (int i = 0; i < 4; i++)
#pragma unroll
                for (int j = 0; j < 4; j++) oacc[i][j] = fmaf(pa[i], vb[j], oacc[i][j]);
        }
    }

    // Final normalize + writeback
#pragma unroll
    for (int i = 0; i < 4; i++) {
        int r = ty * 4 + i;
        float inv_l = 1.0f / l_sh[r];
#pragma unroll
        for (int j = 0; j < 4; j++) {
            int d = tx * 4 + j;
            o[(((size_t)(b * SS + s0q + r)) * HH + h) * DKK + d] = oacc[i][j] * inv_l;
        }
    }
}

// ---------------------------------------------------------------------------
// Launch: QKV GEMMs -> RoPE -> flash attention -> output GEMM
// Inputs: x, mask(ignored: causal known), Wq, bq, Wk, bk, Wv, bv, Wo, bo
// ---------------------------------------------------------------------------
extern "C" void kernel_launch(void* const* d_in, const int* in_sizes, int n_in,
                              void* d_out, int out_size) {
    const float* x  = (const float*)d_in[0];
    const float* Wq = (const float*)d_in[2];
    const float* bq = (const float*)d_in[3];
    const float* Wk = (const float*)d_in[4];
    const float* bk = (const float*)d_in[5];
    const float* Wv = (const float*)d_in[6];
    const float* bv = (const float*)d_in[7];
    const float* Wo = (const float*)d_in[8];
    const float* bo = (const float*)d_in[9];
    float* out = (float*)d_out;

    float *gq, *gk, *gv, *go;
    cudaGetSymbolAddress((void**)&gq, g_q);
    cudaGetSymbolAddress((void**)&gk, g_k);
    cudaGetSymbolAddress((void**)&gv, g_v);
    cudaGetSymbolAddress((void**)&go, g_o);

    const int M = BB * SS;  // 4096
    dim3 blk(256);

    // Q = x @ Wq + bq   (4096 x 1024 x 1024)
    sgemm_bias_kernel<<<dim3(1024 / 128, M / 128), blk>>>(x, Wq, bq, gq, M, 1024, 1024);
    // K = x @ Wk + bk   (4096 x 256 x 1024)
    sgemm_bias_kernel<<<dim3(256 / 128, M / 128), blk>>>(x, Wk, bk, gk, M, 256, 1024);
    // V = x @ Wv + bv
    sgemm_bias_kernel<<<dim3(256 / 128, M / 128), blk>>>(x, Wv, bv, gv, M, 256, 1024);

    // RoPE on Q and K
    int nrope = BB * SS * (HH + KHH) * 32;
    rope_kernel<<<(nrope + 255) / 256, 256>>>(gq, gk);

    // Flash attention
    size_t flash_smem = FLASH_SMEM_FLOATS * sizeof(float);
    cudaFuncSetAttribute(flash_kernel, cudaFuncAttributeMaxDynamicSharedMemorySize,
                         (int)flash_smem);
    flash_kernel<<<dim3(SS / 64, HH, BB), blk, flash_smem>>>(gq, gk, gv, go);

    // out = attn_out @ Wo + bo   (4096 x 1024 x 1024)
    sgemm_bias_kernel<<<dim3(1024 / 128, M / 128), blk>>>(go, Wo, bo, out, M, 1024, 1024);
}

// round 2
// speedup vs baseline: 1.3683x; 1.3683x over previous
#include <cuda_runtime.h>
#include <cuda_bf16.h>
#include <math.h>

// Problem constants (fixed by the reference)
#define BB 2
#define SS 2048
#define DD 1024
#define HH 16
#define KHH 4
#define DKK 64
#define REP 4

// Scratch (device globals; no allocation allowed)
__device__ float g_q[BB * SS * HH * DKK];    // (b,s,h,dk)  4096x1024
__device__ float g_k[BB * SS * KHH * DKK];   // (b,s,kh,dk) 4096x256
__device__ float g_v[BB * SS * KHH * DKK];   // (b,s,kh,dk) 4096x256
__device__ float g_o[BB * SS * HH * DKK];    // attention out, (b,s,h,dk)
__device__ float g_cos[SS * 32];             // rope cos table [s][d]
__device__ float g_sin[SS * 32];             // rope sin table [s][d]

// ---------------------------------------------------------------------------
// SGEMM: C[M,N] = A[M,K] @ B[K,N] + bias[N]
// BM=BN=128, BK=8, 256 threads, 8x8 per-thread micro-tile.
// ---------------------------------------------------------------------------
__global__ __launch_bounds__(256, 2)
void sgemm_bias_kernel(const float* __restrict__ A, const float* __restrict__ Bm,
                       const float* __restrict__ bias, float* __restrict__ C,
                       int M, int N, int K) {
    __shared__ float As[8][128];
    __shared__ float Bs[8][128];

    const int tid = threadIdx.x;
    const int m0 = blockIdx.y * 128;
    const int n0 = blockIdx.x * 128;
    const int ty = tid / 16;
    const int tx = tid % 16;

    const int a_row = tid >> 1;
    const int a_col = (tid & 1) * 4;
    const int b_row = tid >> 5;
    const int b_col = (tid & 31) * 4;

    float acc[8][8];
#pragma unroll
    for (int i = 0; i < 8; i++)
#pragma unroll
        for (int j = 0; j < 8; j++) acc[i][j] = 0.0f;

    for (int k0 = 0; k0 < K; k0 += 8) {
        float4 av = *reinterpret_cast<const float4*>(&A[(m0 + a_row) * K + k0 + a_col]);
        As[a_col + 0][a_row] = av.x;
        As[a_col + 1][a_row] = av.y;
        As[a_col + 2][a_row] = av.z;
        As[a_col + 3][a_row] = av.w;
        *reinterpret_cast<float4*>(&Bs[b_row][b_col]) =
            *reinterpret_cast<const float4*>(&Bm[(k0 + b_row) * N + n0 + b_col]);
        __syncthreads();

#pragma unroll
        for (int kk = 0; kk < 8; kk++) {
            float a[8], b[8];
            *reinterpret_cast<float4*>(a)     = *reinterpret_cast<float4*>(&As[kk][ty * 8]);
            *reinterpret_cast<float4*>(a + 4) = *reinterpret_cast<float4*>(&As[kk][ty * 8 + 4]);
            *reinterpret_cast<float4*>(b)     = *reinterpret_cast<float4*>(&Bs[kk][tx * 8]);
            *reinterpret_cast<float4*>(b + 4) = *reinterpret_cast<float4*>(&Bs[kk][tx * 8 + 4]);
#pragma unroll
            for (int i = 0; i < 8; i++)
#pragma unroll
                for (int j = 0; j < 8; j++) acc[i][j] = fmaf(a[i], b[j], acc[i][j]);
        }
        __syncthreads();
    }

#pragma unroll
    for (int i = 0; i < 8; i++) {
        int row = m0 + ty * 8 + i;
#pragma unroll
        for (int j = 0; j < 8; j++) {
            int col = n0 + tx * 8 + j;
            C[row * N + col] = acc[i][j] + bias[col];
        }
    }
}

// ---------------------------------------------------------------------------
// RoPE table: one thread per (s, d), d < 32. 65536 fp64 evals total.
// ---------------------------------------------------------------------------
__global__ void rope_table_kernel(float* __restrict__ ctab, float* __restrict__ stab) {
    int idx = blockIdx.x * blockDim.x + threadIdx.x;
    if (idx >= SS * 32) return;
    int s = idx >> 5;
    int d = idx & 31;
    double theta = pow(10000.0, -(double)d / 32.0);
    double f = (double)s * theta;
    ctab[idx] = (float)cos(f);
    stab[idx] = (float)sin(f);
}

// ---------------------------------------------------------------------------
// RoPE apply, in-place on g_q and g_k, reading precomputed table.
// One thread per (row, d) pair with d < 32.
// ---------------------------------------------------------------------------
__global__ void rope_apply_kernel(float* __restrict__ q, float* __restrict__ k,
                                  const float* __restrict__ ctab,
                                  const float* __restrict__ stab) {
    const int NQ = BB * SS * HH * 32;
    const int NK = BB * SS * KHH * 32;
    int idx = blockIdx.x * blockDim.x + threadIdx.x;
    if (idx >= NQ + NK) return;

    float* p;
    int s, d;
    if (idx < NQ) {
        int row = idx >> 5;
        d = idx & 31;
        p = q + (size_t)row * DKK;
        s = (row / HH) % SS;
    } else {
        int i2 = idx - NQ;
        int row = i2 >> 5;
        d = i2 & 31;
        p = k + (size_t)row * DKK;
        s = (row / KHH) % SS;
    }

    int t = s * 32 + d;
    float c = ctab[t];
    float sn = stab[t];
    float x1 = p[d];
    float x2 = p[d + 32];
    p[d] = x1 * c - x2 * sn;
    p[d + 32] = x2 * c + x1 * sn;
}

// ---------------------------------------------------------------------------
// Flash attention (causal, GQA). One block per (q_tile=64 rows, h, b).
// ---------------------------------------------------------------------------
#define FLASH_SMEM_FLOATS (4 * 64 * 65 + 3 * 64)

__global__ __launch_bounds__(256, 2)
void flash_kernel(const float* __restrict__ q, const float* __restrict__ k,
                  const float* __restrict__ v, float* __restrict__ o) {
    extern __shared__ float sm[];
    float* Qs = sm;                 // 64 x 65
    float* Ks = sm + 4160;          // 64 x 65
    float* Vs = sm + 8320;          // 64 x 65
    float* Ss = sm + 12480;         // 64 x 65
    float* m_sh = sm + 16640;       // 64
    float* l_sh = m_sh + 64;        // 64
    float* al_sh = l_sh + 64;       // 64

    const int tid = threadIdx.x;
    const int qt = blockIdx.x;
    const int h = blockIdx.y;
    const int b = blockIdx.z;
    const int kh = h >> 2;
    const int s0q = qt * 64;

    for (int t = tid; t < 64 * 16; t += 256) {
        int r = t >> 4;
        int d = (t & 15) * 4;
        float4 val = *reinterpret_cast<const float4*>(
            &q[(((size_t)(b * SS + s0q + r)) * HH + h) * DKK + d]);
        Qs[r * 65 + d + 0] = val.x;
        Qs[r * 65 + d + 1] = val.y;
        Qs[r * 65 + d + 2] = val.z;
        Qs[r * 65 + d + 3] = val.w;
    }
    if (tid < 64) { m_sh[tid] = -1e30f; l_sh[tid] = 0.0f; }

    const int ty = tid / 16;
    const int tx = tid % 16;
    float oacc[4][4];
#pragma unroll
    for (int i = 0; i < 4; i++)
#pragma unroll
        for (int j = 0; j < 4; j++) oacc[i][j] = 0.0f;

    for (int kt = 0; kt <= qt; kt++) {
        const int s0k = kt * 64;
        __syncthreads();

        for (int t = tid; t < 64 * 16; t += 256) {
            int r = t >> 4;
            int d = (t & 15) * 4;
            size_t base = (((size_t)(b * SS + s0k + r)) * KHH + kh) * DKK + d;
            float4 kv = *reinterpret_cast<const float4*>(&k[base]);
            Ks[r * 65 + d + 0] = kv.x;
            Ks[r * 65 + d + 1] = kv.y;
            Ks[r * 65 + d + 2] = kv.z;
            Ks[r * 65 + d + 3] = kv.w;
            float4 vv = *reinterpret_cast<const float4*>(&v[base]);
            Vs[r * 65 + d + 0] = vv.x;
            Vs[r * 65 + d + 1] = vv.y;
            Vs[r * 65 + d + 2] = vv.z;
            Vs[r * 65 + d + 3] = vv.w;
        }
        __syncthreads();

        float sacc[4][4];
#pragma unroll
        for (int i = 0; i < 4; i++)
#pragma unroll
            for (int j = 0; j < 4; j++) sacc[i][j] = 0.0f;

#pragma unroll 8
        for (int kk = 0; kk < 64; kk++) {
            float qa[4], kb[4];
#pragma unroll
            for (int i = 0; i < 4; i++) qa[i] = Qs[(ty * 4 + i) * 65 + kk];
#pragma unroll
            for (int j = 0; j < 4; j++) kb[j] = Ks[(tx * 4 + j) * 65 + kk];
#pragma unroll
            for (int i = 0; i < 4; i++)
#pragma unroll
                for (int j = 0; j < 4; j++) sacc[i][j] = fmaf(qa[i], kb[j], sacc[i][j]);
        }
#pragma unroll
        for (int i = 0; i < 4; i++) {
            int r = ty * 4 + i;
#pragma unroll
            for (int j = 0; j < 4; j++) {
                int c = tx * 4 + j;
                float val = sacc[i][j] * 0.125f;
                if (s0k + c > s0q + r) val = -1e30f;
                Ss[r * 65 + c] = val;
            }
        }
        __syncthreads();

        if (tid < 64) {
            int r = tid;
            float mo = m_sh[r];
            float mx = mo;
#pragma unroll 8
            for (int c = 0; c < 64; c++) mx = fmaxf(mx, Ss[r * 65 + c]);
            float al = __expf(mo - mx);
            float sum = 0.0f;
#pragma unroll 8
            for (int c = 0; c < 64; c++) {
                float p = __expf(Ss[r * 65 + c] - mx);
                Ss[r * 65 + c] = p;
                sum += p;
            }
            l_sh[r] = l_sh[r] * al + sum;
            m_sh[r] = mx;
            al_sh[r] = al;
        }
        __syncthreads();

        float al[4];
#pragma unroll
        for (int i = 0; i < 4; i++) al[i] = al_sh[ty * 4 + i];
#pragma unroll
        for (int i = 0; i < 4; i++)
#pragma unroll
            for (int j = 0; j < 4; j++) oacc[i][j] *= al[i];

#pragma unroll 8
        for (int kk = 0; kk < 64; kk++) {
            float pa[4], vb[4];
#pragma unroll
            for (int i = 0; i < 4; i++) pa[i] = Ss[(ty * 4 + i) * 65 + kk];
#pragma unroll
            for (int j = 0; j < 4; j++) vb[j] = Vs[kk * 65 + tx * 4 + j];
#pragma unroll
            for (int i = 0; i < 4; i++)
#pragma unroll
                for (int j = 0; j < 4; j++) oacc[i][j] = fmaf(pa[i], vb[j], oacc[i][j]);
        }
    }

#pragma unroll
    for (int i = 0; i < 4; i++) {
        int r = ty * 4 + i;
        float inv_l = 1.0f / l_sh[r];
#pragma unroll
        for (int j = 0; j < 4; j++) {
            int d = tx * 4 + j;
            o[(((size_t)(b * SS + s0q + r)) * HH + h) * DKK + d] = oacc[i][j] * inv_l;
        }
    }
}

// ---------------------------------------------------------------------------
// Launch
// ---------------------------------------------------------------------------
extern "C" void kernel_launch(void* const* d_in, const int* in_sizes, int n_in,
                              void* d_out, int out_size) {
    const float* x  = (const float*)d_in[0];
    const float* Wq = (const float*)d_in[2];
    const float* bq = (const float*)d_in[3];
    const float* Wk = (const float*)d_in[4];
    const float* bk = (const float*)d_in[5];
    const float* Wv = (const float*)d_in[6];
    const float* bv = (const float*)d_in[7];
    const float* Wo = (const float*)d_in[8];
    const float* bo = (const float*)d_in[9];
    float* out = (float*)d_out;

    float *gq, *gk, *gv, *go, *gc, *gs;
    cudaGetSymbolAddress((void**)&gq, g_q);
    cudaGetSymbolAddress((void**)&gk, g_k);
    cudaGetSymbolAddress((void**)&gv, g_v);
    cudaGetSymbolAddress((void**)&go, g_o);
    cudaGetSymbolAddress((void**)&gc, g_cos);
    cudaGetSymbolAddress((void**)&gs, g_sin);

    const int M = BB * SS;  // 4096
    dim3 blk(256);

    // RoPE table (independent of GEMMs; launch first)
    rope_table_kernel<<<(SS * 32 + 255) / 256, 256>>>(gc, gs);

    // Q = x @ Wq + bq   (4096 x 1024 x 1024)
    sgemm_bias_kernel<<<dim3(1024 / 128, M / 128), blk>>>(x, Wq, bq, gq, M, 1024, 1024);
    // K = x @ Wk + bk   (4096 x 256 x 1024)
    sgemm_bias_kernel<<<dim3(256 / 128, M / 128), blk>>>(x, Wk, bk, gk, M, 256, 1024);
    // V = x @ Wv + bv
    sgemm_bias_kernel<<<dim3(256 / 128, M / 128), blk>>>(x, Wv, bv, gv, M, 256, 1024);

    // RoPE apply on Q and K
    int nrope = BB * SS * (HH + KHH) * 32;
    rope_apply_kernel<<<(nrope + 255) / 256, 256>>>(gq, gk, gc, gs);

    // Flash attention
    size_t flash_smem = FLASH_SMEM_FLOATS * sizeof(float);
    cudaFuncSetAttribute(flash_kernel, cudaFuncAttributeMaxDynamicSharedMemorySize,
                         (int)flash_smem);
    flash_kernel<<<dim3(SS / 64, HH, BB), blk, flash_smem>>>(gq, gk, gv, go);

    // out = attn_out @ Wo + bo   (4096 x 1024 x 1024)
    sgemm_bias_kernel<<<dim3(1024 / 128, M / 128), blk>>>(go, Wo, bo, out, M, 1024, 1024);
}

// round 3
// speedup vs baseline: 1.7444x; 1.2748x over previous
#include <cuda_runtime.h>
#include <cuda_bf16.h>
#include <mma.h>
#include <math.h>

using namespace nvcuda;

// Problem constants (fixed by the reference)
#define BB 2
#define SS 2048
#define DD 1024
#define HH 16
#define KHH 4
#define DKK 64
#define REP 4

// fp32 scratch
__device__ float g_q[BB * SS * HH * DKK];    // (b,s,h,dk)  4096x1024
__device__ float g_k[BB * SS * KHH * DKK];   // (b,s,kh,dk) 4096x256
__device__ float g_v[BB * SS * KHH * DKK];   // (b,s,kh,dk) 4096x256
__device__ float g_o[BB * SS * HH * DKK];    // attention out, (b,s,h,dk)
__device__ float g_cos[SS * 32];
__device__ float g_sin[SS * 32];

// bf16 split scratch
__device__ __nv_bfloat16 g_xhi[BB * SS * DD],  g_xlo[BB * SS * DD];
__device__ __nv_bfloat16 g_ohi[BB * SS * DD],  g_olo[BB * SS * DD];
__device__ __nv_bfloat16 g_wqhi[DD * DD],      g_wqlo[DD * DD];
__device__ __nv_bfloat16 g_wkhi[DD * 256],     g_wklo[DD * 256];
__device__ __nv_bfloat16 g_wvhi[DD * 256],     g_wvlo[DD * 256];
__device__ __nv_bfloat16 g_wohi[DD * DD],      g_wolo[DD * DD];

// ---------------------------------------------------------------------------
// Split fp32 -> (bf16 hi, bf16 lo)
// ---------------------------------------------------------------------------
__global__ void split_kernel(const float* __restrict__ in,
                             __nv_bfloat16* __restrict__ hi,
                             __nv_bfloat16* __restrict__ lo, int n) {
    int i = blockIdx.x * blockDim.x + threadIdx.x;
    if (i >= n) return;
    float f = in[i];
    __nv_bfloat16 h = __float2bfloat16(f);
    float r = f - __bfloat162float(h);
    hi[i] = h;
    lo[i] = __float2bfloat16(r);
}

// ---------------------------------------------------------------------------
// bf16x3 GEMM: C[M,N] = Ahi@Bhi + Ahi@Blo + Alo@Bhi + bias
// Block tile 128x128, BK=16, 256 threads = 8 warps (4 in M x 2 in N),
// warp tile 32x64 = 2x4 wmma 16x16x16 f32 accumulators.
// Requires M%128==0, N%128==0, K%16==0.
// ---------------------------------------------------------------------------
__global__ __launch_bounds__(256, 2)
void gemm_bf16x3_bias(const __nv_bfloat16* __restrict__ Ahi,
                      const __nv_bfloat16* __restrict__ Alo,
                      const __nv_bfloat16* __restrict__ Bhi,
                      const __nv_bfloat16* __restrict__ Blo,
                      const float* __restrict__ bias, float* __restrict__ C,
                      int M, int N, int K) {
    __shared__ __align__(16) __nv_bfloat16 sAhi[128][24];
    __shared__ __align__(16) __nv_bfloat16 sAlo[128][24];
    __shared__ __align__(16) __nv_bfloat16 sBhi[16][136];
    __shared__ __align__(16) __nv_bfloat16 sBlo[16][136];
    __shared__ __align__(16) float stage[8][16][20];

    const int tid = threadIdx.x;
    const int warp = tid >> 5;
    const int m0 = blockIdx.y * 128;
    const int n0 = blockIdx.x * 128;
    const int wm = warp >> 1;        // 0..3 -> 32 rows each
    const int wn = warp & 1;         // 0..1 -> 64 cols each

    wmma::fragment<wmma::accumulator, 16, 16, 16, float> acc[2][4];
#pragma unroll
    for (int i = 0; i < 2; i++)
#pragma unroll
        for (int j = 0; j < 4; j++) wmma::fill_fragment(acc[i][j], 0.0f);

    for (int k0 = 0; k0 < K; k0 += 16) {
        // Load A tiles: 128 rows x 16 cols, 4 bf16 (8B) per slot
        for (int idx = tid; idx < 128 * 4; idx += 256) {
            int r = idx >> 2;
            int c = (idx & 3) * 4;
            size_t g = (size_t)(m0 + r) * K + k0 + c;
            *reinterpret_cast<uint2*>(&sAhi[r][c]) =
                *reinterpret_cast<const uint2*>(&Ahi[g]);
            *reinterpret_cast<uint2*>(&sAlo[r][c]) =
                *reinterpret_cast<const uint2*>(&Alo[g]);
        }
        // Load B tiles: 16 rows x 128 cols, 8 bf16 (16B) per slot
        for (int idx = tid; idx < 16 * 16; idx += 256) {
            int r = idx >> 4;
            int c = (idx & 15) * 8;
            size_t g = (size_t)(k0 + r) * N + n0 + c;
            *reinterpret_cast<uint4*>(&sBhi[r][c]) =
                *reinterpret_cast<const uint4*>(&Bhi[g]);
            *reinterpret_cast<uint4*>(&sBlo[r][c]) =
                *reinterpret_cast<const uint4*>(&Blo[g]);
        }
        __syncthreads();

        wmma::fragment<wmma::matrix_a, 16, 16, 16, __nv_bfloat16, wmma::row_major> ahi[2], alo[2];
#pragma unroll
        for (int i = 0; i < 2; i++) {
            wmma::load_matrix_sync(ahi[i], &sAhi[wm * 32 + i * 16][0], 24);
            wmma::load_matrix_sync(alo[i], &sAlo[wm * 32 + i * 16][0], 24);
        }
#pragma unroll
        for (int j = 0; j < 4; j++) {
            wmma::fragment<wmma::matrix_b, 16, 16, 16, __nv_bfloat16, wmma::row_major> bhi, blo;
            wmma::load_matrix_sync(bhi, &sBhi[0][wn * 64 + j * 16], 136);
            wmma::load_matrix_sync(blo, &sBlo[0][wn * 64 + j * 16], 136);
#pragma unroll
            for (int i = 0; i < 2; i++) {
                wmma::mma_sync(acc[i][j], ahi[i], bhi, acc[i][j]);
                wmma::mma_sync(acc[i][j], ahi[i], blo, acc[i][j]);
                wmma::mma_sync(acc[i][j], alo[i], bhi, acc[i][j]);
            }
        }
        __syncthreads();
    }

    // Epilogue: stage each 16x16 tile in smem, add bias, write out
    const int lane = tid & 31;
#pragma unroll
    for (int i = 0; i < 2; i++) {
#pragma unroll
        for (int j = 0; j < 4; j++) {
            wmma::store_matrix_sync(&stage[warp][0][0], acc[i][j], 20, wmma::mem_row_major);
            __syncwarp();
            int row0 = m0 + wm * 32 + i * 16;
            int col0 = n0 + wn * 64 + j * 16;
#pragma unroll
            for (int e = 0; e < 8; e++) {
                int t = e * 32 + lane;
                int r = t >> 4;
                int c = t & 15;
                C[(size_t)(row0 + r) * N + col0 + c] = stage[warp][r][c] + bias[col0 + c];
            }
            __syncwarp();
        }
    }
}

// ---------------------------------------------------------------------------
// RoPE table: one thread per (s, d), d < 32.
// ---------------------------------------------------------------------------
__global__ void rope_table_kernel(float* __restrict__ ctab, float* __restrict__ stab) {
    int idx = blockIdx.x * blockDim.x + threadIdx.x;
    if (idx >= SS * 32) return;
    int s = idx >> 5;
    int d = idx & 31;
    double theta = pow(10000.0, -(double)d / 32.0);
    double f = (double)s * theta;
    ctab[idx] = (float)cos(f);
    stab[idx] = (float)sin(f);
}

// ---------------------------------------------------------------------------
// RoPE apply, in-place on g_q and g_k.
// ---------------------------------------------------------------------------
__global__ void rope_apply_kernel(float* __restrict__ q, float* __restrict__ k,
                                  const float* __restrict__ ctab,
                                  const float* __restrict__ stab) {
    const int NQ = BB * SS * HH * 32;
    const int NK = BB * SS * KHH * 32;
    int idx = blockIdx.x * blockDim.x + threadIdx.x;
    if (idx >= NQ + NK) return;

    float* p;
    int s, d;
    if (idx < NQ) {
        int row = idx >> 5;
        d = idx & 31;
        p = q + (size_t)row * DKK;
        s = (row / HH) % SS;
    } else {
        int i2 = idx - NQ;
        int row = i2 >> 5;
        d = i2 & 31;
        p = k + (size_t)row * DKK;
        s = (row / KHH) % SS;
    }

    int t = s * 32 + d;
    float c = ctab[t];
    float sn = stab[t];
    float x1 = p[d];
    float x2 = p[d + 32];
    p[d] = x1 * c - x2 * sn;
    p[d + 32] = x2 * c + x1 * sn;
}

// ---------------------------------------------------------------------------
// Flash attention (causal, GQA). One block per (q_tile=64 rows, h, b).
// ---------------------------------------------------------------------------
#define FLASH_SMEM_FLOATS (4 * 64 * 65 + 3 * 64)

__global__ __launch_bounds__(256, 2)
void flash_kernel(const float* __restrict__ q, const float* __restrict__ k,
                  const float* __restrict__ v, float* __restrict__ o) {
    extern __shared__ float sm[];
    float* Qs = sm;                 // 64 x 65
    float* Ks = sm + 4160;          // 64 x 65
    float* Vs = sm + 8320;          // 64 x 65
    float* Ss = sm + 12480;         // 64 x 65
    float* m_sh = sm + 16640;       // 64
    float* l_sh = m_sh + 64;        // 64
    float* al_sh = l_sh + 64;       // 64

    const int tid = threadIdx.x;
    const int qt = blockIdx.x;
    const int h = blockIdx.y;
    const int b = blockIdx.z;
    const int kh = h >> 2;
    const int s0q = qt * 64;

    for (int t = tid; t < 64 * 16; t += 256) {
        int r = t >> 4;
        int d = (t & 15) * 4;
        float4 val = *reinterpret_cast<const float4*>(
            &q[(((size_t)(b * SS + s0q + r)) * HH + h) * DKK + d]);
        Qs[r * 65 + d + 0] = val.x;
        Qs[r * 65 + d + 1] = val.y;
        Qs[r * 65 + d + 2] = val.z;
        Qs[r * 65 + d + 3] = val.w;
    }
    if (tid < 64) { m_sh[tid] = -1e30f; l_sh[tid] = 0.0f; }

    const int ty = tid / 16;
    const int tx = tid % 16;
    float oacc[4][4];
#pragma unroll
    for (int i = 0; i < 4; i++)
#pragma unroll
        for (int j = 0; j < 4; j++) oacc[i][j] = 0.0f;

    for (int kt = 0; kt <= qt; kt++) {
        const int s0k = kt * 64;
        __syncthreads();

        for (int t = tid; t < 64 * 16; t += 256) {
            int r = t >> 4;
            int d = (t & 15) * 4;
            size_t base = (((size_t)(b * SS + s0k + r)) * KHH + kh) * DKK + d;
            float4 kv = *reinterpret_cast<const float4*>(&k[base]);
            Ks[r * 65 + d + 0] = kv.x;
            Ks[r * 65 + d + 1] = kv.y;
            Ks[r * 65 + d + 2] = kv.z;
            Ks[r * 65 + d + 3] = kv.w;
            float4 vv = *reinterpret_cast<const float4*>(&v[base]);
            Vs[r * 65 + d + 0] = vv.x;
            Vs[r * 65 + d + 1] = vv.y;
            Vs[r * 65 + d + 2] = vv.z;
            Vs[r * 65 + d + 3] = vv.w;
        }
        __syncthreads();

        float sacc[4][4];
#pragma unroll
        for (int i = 0; i < 4; i++)
#pragma unroll
            for (int j = 0; j < 4; j++) sacc[i][j] = 0.0f;

#pragma unroll 8
        for (int kk = 0; kk < 64; kk++) {
            float qa[4], kb[4];
#pragma unroll
            for (int i = 0; i < 4; i++) qa[i] = Qs[(ty * 4 + i) * 65 + kk];
#pragma unroll
            for (int j = 0; j < 4; j++) kb[j] = Ks[(tx * 4 + j) * 65 + kk];
#pragma unroll
            for (int i = 0; i < 4; i++)
#pragma unroll
                for (int j = 0; j < 4; j++) sacc[i][j] = fmaf(qa[i], kb[j], sacc[i][j]);
        }
#pragma unroll
        for (int i = 0; i < 4; i++) {
            int r = ty * 4 + i;
#pragma unroll
            for (int j = 0; j < 4; j++) {
                int c = tx * 4 + j;
                float val = sacc[i][j] * 0.125f;
                if (s0k + c > s0q + r) val = -1e30f;
                Ss[r * 65 + c] = val;
            }
        }
        __syncthreads();

        if (tid < 64) {
            int r = tid;
            float mo = m_sh[r];
            float mx = mo;
#pragma unroll 8
            for (int c = 0; c < 64; c++) mx = fmaxf(mx, Ss[r * 65 + c]);
            float al = __expf(mo - mx);
            float sum = 0.0f;
#pragma unroll 8
            for (int c = 0; c < 64; c++) {
                float p = __expf(Ss[r * 65 + c] - mx);
                Ss[r * 65 + c] = p;
                sum += p;
            }
            l_sh[r] = l_sh[r] * al + sum;
            m_sh[r] = mx;
            al_sh[r] = al;
        }
        __syncthreads();

        float al[4];
#pragma unroll
        for (int i = 0; i < 4; i++) al[i] = al_sh[ty * 4 + i];
#pragma unroll
        for (int i = 0; i < 4; i++)
#pragma unroll
            for (int j = 0; j < 4; j++) oacc[i][j] *= al[i];

#pragma unroll 8
        for (int kk = 0; kk < 64; kk++) {
            float pa[4], vb[4];
#pragma unroll
            for (int i = 0; i < 4; i++) pa[i] = Ss[(ty * 4 + i) * 65 + kk];
#pragma unroll
            for (int j = 0; j < 4; j++) vb[j] = Vs[kk * 65 + tx * 4 + j];
#pragma unroll
            for (int i = 0; i < 4; i++)
#pragma unroll
                for (int j = 0; j < 4; j++) oacc[i][j] = fmaf(pa[i], vb[j], oacc[i][j]);
        }
    }

#pragma unroll
    for (int i = 0; i < 4; i++) {
        int r = ty * 4 + i;
        float inv_l = 1.0f / l_sh[r];
#pragma unroll
        for (int j = 0; j < 4; j++) {
            int d = tx * 4 + j;
            o[(((size_t)(b * SS + s0q + r)) * HH + h) * DKK + d] = oacc[i][j] * inv_l;
        }
    }
}

// ---------------------------------------------------------------------------
// Launch
// ---------------------------------------------------------------------------
extern "C" void kernel_launch(void* const* d_in, const int* in_sizes, int n_in,
                              void* d_out, int out_size) {
    const float* x  = (const float*)d_in[0];
    const float* Wq = (const float*)d_in[2];
    const float* bq = (const float*)d_in[3];
    const float* Wk = (const float*)d_in[4];
    const float* bk = (const float*)d_in[5];
    const float* Wv = (const float*)d_in[6];
    const float* bv = (const float*)d_in[7];
    const float* Wo = (const float*)d_in[8];
    const float* bo = (const float*)d_in[9];
    float* out = (float*)d_out;

    float *gq, *gk, *gv, *go, *gc, *gs;
    cudaGetSymbolAddress((void**)&gq, g_q);
    cudaGetSymbolAddress((void**)&gk, g_k);
    cudaGetSymbolAddress((void**)&gv, g_v);
    cudaGetSymbolAddress((void**)&go, g_o);
    cudaGetSymbolAddress((void**)&gc, g_cos);
    cudaGetSymbolAddress((void**)&gs, g_sin);

    __nv_bfloat16 *xhi, *xlo, *ohi, *olo;
    __nv_bfloat16 *wqhi, *wqlo, *wkhi, *wklo, *wvhi, *wvlo, *wohi, *wolo;
    cudaGetSymbolAddress((void**)&xhi, g_xhi);
    cudaGetSymbolAddress((void**)&xlo, g_xlo);
    cudaGetSymbolAddress((void**)&ohi, g_ohi);
    cudaGetSymbolAddress((void**)&olo, g_olo);
    cudaGetSymbolAddress((void**)&wqhi, g_wqhi);
    cudaGetSymbolAddress((void**)&wqlo, g_wqlo);
    cudaGetSymbolAddress((void**)&wkhi, g_wkhi);
    cudaGetSymbolAddress((void**)&wklo, g_wklo);
    cudaGetSymbolAddress((void**)&wvhi, g_wvhi);
    cudaGetSymbolAddress((void**)&wvlo, g_wvlo);
    cudaGetSymbolAddress((void**)&wohi, g_wohi);
    cudaGetSymbolAddress((void**)&wolo, g_wolo);

    const int M = BB * SS;  // 4096
    dim3 blk(256);

    // RoPE table
    rope_table_kernel<<<(SS * 32 + 255) / 256, 256>>>(gc, gs);

    // Splits
    int nx = M * DD;
    split_kernel<<<(nx + 255) / 256, 256>>>(x, xhi, xlo, nx);
    split_kernel<<<(DD * DD + 255) / 256, 256>>>(Wq, wqhi, wqlo, DD * DD);
    split_kernel<<<(DD * 256 + 255) / 256, 256>>>(Wk, wkhi, wklo, DD * 256);
    split_kernel<<<(DD * 256 + 255) / 256, 256>>>(Wv, wvhi, wvlo, DD * 256);
    split_kernel<<<(DD * DD + 255) / 256, 256>>>(Wo, wohi, wolo, DD * DD);

    // QKV projections (tensor cores)
    gemm_bf16x3_bias<<<dim3(1024 / 128, M / 128), blk>>>(xhi, xlo, wqhi, wqlo, bq, gq, M, 1024, 1024);
    gemm_bf16x3_bias<<<dim3(256 / 128, M / 128), blk>>>(xhi, xlo, wkhi, wklo, bk, gk, M, 256, 1024);
    gemm_bf16x3_bias<<<dim3(256 / 128, M / 128), blk>>>(xhi, xlo, wvhi, wvlo, bv, gv, M, 256, 1024);

    // RoPE apply on Q and K
    int nrope = BB * SS * (HH + KHH) * 32;
    rope_apply_kernel<<<(nrope + 255) / 256, 256>>>(gq, gk, gc, gs);

    // Flash attention (fp32)
    size_t flash_smem = FLASH_SMEM_FLOATS * sizeof(float);
    cudaFuncSetAttribute(flash_kernel, cudaFuncAttributeMaxDynamicSharedMemorySize,
                         (int)flash_smem);
    flash_kernel<<<dim3(SS / 64, HH, BB), blk, flash_smem>>>(gq, gk, gv, go);

    // Split attention output, then output projection (tensor cores)
    split_kernel<<<(nx + 255) / 256, 256>>>(go, ohi, olo, nx);
    gemm_bf16x3_bias<<<dim3(1024 / 128, M / 128), blk>>>(ohi, olo, wohi, wolo, bo, out, M, 1024, 1024);
}

// round 5
// speedup vs baseline: 1.9613x; 1.1243x over previous
#include <cuda_runtime.h>
#include <cuda_bf16.h>
#include <mma.h>
#include <math.h>
#include <cstdint>

using namespace nvcuda;

#define BB 2
#define SS 2048
#define DD 1024
#define HH 16
#define KHH 4
#define DKK 64
#define REP 4
#define NQKV 1536   // 1024 Q | 256 K | 256 V

// fp32 scratch
__device__ float g_qkv[BB * SS * NQKV];      // packed Q|K|V per (b,s) row
__device__ float g_o[BB * SS * HH * DKK];    // attention out, (b,s,h,dk)
__device__ float g_cos[SS * 32];
__device__ float g_sin[SS * 32];
__device__ float g_bqkv[NQKV];

// bf16 split scratch
__device__ __nv_bfloat16 g_xhi[BB * SS * DD],   g_xlo[BB * SS * DD];
__device__ __nv_bfloat16 g_ohi[BB * SS * DD],   g_olo[BB * SS * DD];
__device__ __nv_bfloat16 g_wqkvhi[DD * NQKV],   g_wqkvlo[DD * NQKV];
__device__ __nv_bfloat16 g_wohi[DD * DD],       g_wolo[DD * DD];

// ---------------------------------------------------------------------------
// cp.async helpers
// ---------------------------------------------------------------------------
__device__ __forceinline__ void cp_async16(void* sptr, const void* gptr) {
    unsigned int s = (unsigned int)__cvta_generic_to_shared(sptr);
    asm volatile("cp.async.cg.shared.global [%0], [%1], 16;\n" :: "r"(s), "l"(gptr));
}
__device__ __forceinline__ void cp_commit() {
    asm volatile("cp.async.commit_group;\n");
}
__device__ __forceinline__ void cp_wait1() {
    asm volatile("cp.async.wait_group 1;\n");
}
__device__ __forceinline__ void cp_wait0() {
    asm volatile("cp.async.wait_group 0;\n");
}

// ---------------------------------------------------------------------------
// Split fp32 -> (bf16 hi, bf16 lo)
// ---------------------------------------------------------------------------
__global__ void split_kernel(const float* __restrict__ in,
                             __nv_bfloat16* __restrict__ hi,
                             __nv_bfloat16* __restrict__ lo, int n) {
    int i = blockIdx.x * blockDim.x + threadIdx.x;
    if (i >= n) return;
    float f = in[i];
    __nv_bfloat16 h = __float2bfloat16(f);
    hi[i] = h;
    lo[i] = __float2bfloat16(f - __bfloat162float(h));
}

// Pack Wq|Wk|Wv -> [1024][1536] hi/lo, and bq|bk|bv -> g_bqkv
__global__ void pack_wqkv_kernel(const float* __restrict__ Wq, const float* __restrict__ Wk,
                                 const float* __restrict__ Wv, const float* __restrict__ bq,
                                 const float* __restrict__ bk, const float* __restrict__ bv,
                                 __nv_bfloat16* __restrict__ hi, __nv_bfloat16* __restrict__ lo,
                                 float* __restrict__ bqkv) {
    int i = blockIdx.x * blockDim.x + threadIdx.x;
    int n = DD * NQKV;
    if (i < NQKV) {
        int c = i;
        bqkv[c] = (c < 1024) ? bq[c] : (c < 1280 ? bk[c - 1024] : bv[c - 1280]);
    }
    if (i >= n) return;
    int row = i / NQKV;
    int col = i % NQKV;
    float f;
    if (col < 1024)      f = Wq[row * 1024 + col];
    else if (col < 1280) f = Wk[row * 256 + col - 1024];
    else                 f = Wv[row * 256 + col - 1280];
    __nv_bfloat16 h = __float2bfloat16(f);
    hi[i] = h;
    lo[i] = __float2bfloat16(f - __bfloat162float(h));
}

// ---------------------------------------------------------------------------
// bf16x3 GEMM v2: C[M,N] = Ahi@Bhi + Ahi@Blo + Alo@Bhi + bias
// 128x128 block tile, BK=32, cp.async double-buffered, 256 thr = 8 warps
// (4 in M x 2 in N), warp tile 32x64 = 2x4 wmma 16x16x16 f32.
// ---------------------------------------------------------------------------
#define GSM_A_BYTES (2 * 2 * 128 * 40 * 2)
#define GSM_B_BYTES (2 * 2 * 32 * 136 * 2)
#define GSM_STAGE_BYTES (8 * 16 * 20 * 4)
#define GSM_TOTAL (GSM_A_BYTES + GSM_B_BYTES + GSM_STAGE_BYTES)

__device__ __forceinline__ int sA_idx(int buf, int part, int r, int c) {
    return ((buf * 2 + part) * 128 + r) * 40 + c;
}
__device__ __forceinline__ int sB_idx(int buf, int part, int r, int c) {
    return ((buf * 2 + part) * 32 + r) * 136 + c;
}

__global__ __launch_bounds__(256)
void gemm_bf16x3_v2(const __nv_bfloat16* __restrict__ Ahi,
                    const __nv_bfloat16* __restrict__ Alo,
                    const __nv_bfloat16* __restrict__ Bhi,
                    const __nv_bfloat16* __restrict__ Blo,
                    const float* __restrict__ bias, float* __restrict__ C,
                    int M, int N, int K) {
    extern __shared__ __align__(16) unsigned char smraw[];
    __nv_bfloat16* sA = (__nv_bfloat16*)smraw;
    __nv_bfloat16* sB = (__nv_bfloat16*)(smraw + GSM_A_BYTES);
    float* stage = (float*)(smraw + GSM_A_BYTES + GSM_B_BYTES);

    const int tid = threadIdx.x;
    const int warp = tid >> 5;
    const int lane = tid & 31;
    const int m0 = blockIdx.y * 128;
    const int n0 = blockIdx.x * 128;
    const int wm = warp >> 1;
    const int wn = warp & 1;

    wmma::fragment<wmma::accumulator, 16, 16, 16, float> acc[2][4];
#pragma unroll
    for (int i = 0; i < 2; i++)
#pragma unroll
        for (int j = 0; j < 4; j++) wmma::fill_fragment(acc[i][j], 0.0f);

    const int nk = K / 32;

    auto load_stage = [&](int buf, int k0) {
#pragma unroll
        for (int c = tid; c < 512; c += 256) {
            int r = c >> 2;
            int cc = (c & 3) * 8;
            size_t g = (size_t)(m0 + r) * K + k0 + cc;
            cp_async16(&sA[sA_idx(buf, 0, r, cc)], &Ahi[g]);
            cp_async16(&sA[sA_idx(buf, 1, r, cc)], &Alo[g]);
        }
#pragma unroll
        for (int c = tid; c < 512; c += 256) {
            int r = c >> 4;
            int cc = (c & 15) * 8;
            size_t g = (size_t)(k0 + r) * N + n0 + cc;
            cp_async16(&sB[sB_idx(buf, 0, r, cc)], &Bhi[g]);
            cp_async16(&sB[sB_idx(buf, 1, r, cc)], &Blo[g]);
        }
        cp_commit();
    };

    load_stage(0, 0);

    for (int kt = 0; kt < nk; kt++) {
        int buf = kt & 1;
        if (kt + 1 < nk) {
            load_stage(buf ^ 1, (kt + 1) * 32);
            cp_wait1();
        } else {
            cp_wait0();
        }
        __syncthreads();

#pragma unroll
        for (int ks = 0; ks < 2; ks++) {
            wmma::fragment<wmma::matrix_a, 16, 16, 16, __nv_bfloat16, wmma::row_major> ahi[2], alo[2];
#pragma unroll
            for (int i = 0; i < 2; i++) {
                wmma::load_matrix_sync(ahi[i], &sA[sA_idx(buf, 0, wm * 32 + i * 16, ks * 16)], 40);
                wmma::load_matrix_sync(alo[i], &sA[sA_idx(buf, 1, wm * 32 + i * 16, ks * 16)], 40);
            }
#pragma unroll
            for (int j = 0; j < 4; j++) {
                wmma::fragment<wmma::matrix_b, 16, 16, 16, __nv_bfloat16, wmma::row_major> bhi, blo;
                wmma::load_matrix_sync(bhi, &sB[sB_idx(buf, 0, ks * 16, wn * 64 + j * 16)], 136);
                wmma::load_matrix_sync(blo, &sB[sB_idx(buf, 1, ks * 16, wn * 64 + j * 16)], 136);
#pragma unroll
                for (int i = 0; i < 2; i++) {
                    wmma::mma_sync(acc[i][j], ahi[i], bhi, acc[i][j]);
                    wmma::mma_sync(acc[i][j], ahi[i], blo, acc[i][j]);
                    wmma::mma_sync(acc[i][j], alo[i], bhi, acc[i][j]);
                }
            }
        }
        __syncthreads();
    }

    float* wstage = stage + warp * 16 * 20;
#pragma unroll
    for (int i = 0; i < 2; i++) {
#pragma unroll
        for (int j = 0; j < 4; j++) {
            wmma::store_matrix_sync(wstage, acc[i][j], 20, wmma::mem_row_major);
            __syncwarp();
            int row0 = m0 + wm * 32 + i * 16;
            int col0 = n0 + wn * 64 + j * 16;
#pragma unroll
            for (int e = 0; e < 8; e++) {
                int t = e * 32 + lane;
                int r = t >> 4;
                int c = t & 15;
                C[(size_t)(row0 + r) * N + col0 + c] = wstage[r * 20 + c] + bias[col0 + c];
            }
            __syncwarp();
        }
    }
}

// ---------------------------------------------------------------------------
// RoPE table
// ---------------------------------------------------------------------------
__global__ void rope_table_kernel(float* __restrict__ ctab, float* __restrict__ stab) {
    int idx = blockIdx.x * blockDim.x + threadIdx.x;
    if (idx >= SS * 32) return;
    int s = idx >> 5;
    int d = idx & 31;
    double theta = pow(10000.0, -(double)d / 32.0);
    double f = (double)s * theta;
    ctab[idx] = (float)cos(f);
    stab[idx] = (float)sin(f);
}

// ---------------------------------------------------------------------------
// RoPE apply on packed qkv layout.
// ---------------------------------------------------------------------------
__global__ void rope_apply_kernel(float* __restrict__ qkv,
                                  const float* __restrict__ ctab,
                                  const float* __restrict__ stab) {
    const int NQp = BB * SS * HH * 32;
    const int NKp = BB * SS * KHH * 32;
    int idx = blockIdx.x * blockDim.x + threadIdx.x;
    if (idx >= NQp + NKp) return;

    float* p;
    int s, d;
    if (idx < NQp) {
        int bs = idx / (HH * 32);
        int rem = idx % (HH * 32);
        int h = rem >> 5;
        d = rem & 31;
        s = bs % SS;
        p = qkv + (size_t)bs * NQKV + h * DKK;
    } else {
        int i2 = idx - NQp;
        int bs = i2 / (KHH * 32);
        int rem = i2 % (KHH * 32);
        int kh = rem >> 5;
        d = rem & 31;
        s = bs % SS;
        p = qkv + (size_t)bs * NQKV + 1024 + kh * DKK;
    }

    int t = s * 32 + d;
    float c = ctab[t];
    float sn = stab[t];
    float x1 = p[d];
    float x2 = p[d + 32];
    p[d] = x1 * c - x2 * sn;
    p[d + 32] = x2 * c + x1 * sn;
}

// ---------------------------------------------------------------------------
// Flash attention (causal, GQA), fp32, reading packed qkv.
// ---------------------------------------------------------------------------
#define FLASH_SMEM_FLOATS (4 * 64 * 65 + 3 * 64)

__global__ __launch_bounds__(256, 2)
void flash_kernel(const float* __restrict__ qkv, float* __restrict__ o) {
    extern __shared__ float sm[];
    float* Qs = sm;
    float* Ks = sm + 4160;
    float* Vs = sm + 8320;
    float* Ss = sm + 12480;
    float* m_sh = sm + 16640;
    float* l_sh = m_sh + 64;
    float* al_sh = l_sh + 64;

    const int tid = threadIdx.x;
    const int qt = blockIdx.x;
    const int h = blockIdx.y;
    const int b = blockIdx.z;
    const int kh = h >> 2;
    const int s0q = qt * 64;

    for (int t = tid; t < 64 * 16; t += 256) {
        int r = t >> 4;
        int d = (t & 15) * 4;
        float4 val = *reinterpret_cast<const float4*>(
            &qkv[(size_t)(b * SS + s0q + r) * NQKV + h * DKK + d]);
        Qs[r * 65 + d + 0] = val.x;
        Qs[r * 65 + d + 1] = val.y;
        Qs[r * 65 + d + 2] = val.z;
        Qs[r * 65 + d + 3] = val.w;
    }
    if (tid < 64) { m_sh[tid] = -1e30f; l_sh[tid] = 0.0f; }

    const int ty = tid / 16;
    const int tx = tid % 16;
    float oacc[4][4];
#pragma unroll
    for (int i = 0; i < 4; i++)
#pragma unroll
        for (int j = 0; j < 4; j++) oacc[i][j] = 0.0f;

    for (int kt = 0; kt <= qt; kt++) {
        const int s0k = kt * 64;
        __syncthreads();

        for (int t = tid; t < 64 * 16; t += 256) {
            int r = t >> 4;
            int d = (t & 15) * 4;
            size_t base = (size_t)(b * SS + s0k + r) * NQKV + 1024 + kh * DKK + d;
            float4 kv = *reinterpret_cast<const float4*>(&qkv[base]);
            Ks[r * 65 + d + 0] = kv.x;
            Ks[r * 65 + d + 1] = kv.y;
            Ks[r * 65 + d + 2] = kv.z;
            Ks[r * 65 + d + 3] = kv.w;
            float4 vv = *reinterpret_cast<const float4*>(&qkv[base + 256]);
            Vs[r * 65 + d + 0] = vv.x;
            Vs[r * 65 + d + 1] = vv.y;
            Vs[r * 65 + d + 2] = vv.z;
            Vs[r * 65 + d + 3] = vv.w;
        }
        __syncthreads();

        float sacc[4][4];
#pragma unroll
        for (int i = 0; i < 4; i++)
#pragma unroll
            for (int j = 0; j < 4; j++) sacc[i][j] = 0.0f;

#pragma unroll 8
        for (int kk = 0; kk < 64; kk++) {
            float qa[4], kb[4];
#pragma unroll
            for (int i = 0; i < 4; i++) qa[i] = Qs[(ty * 4 + i) * 65 + kk];
#pragma unroll
            for (int j = 0; j < 4; j++) kb[j] = Ks[(tx * 4 + j) * 65 + kk];
#pragma unroll
            for (int i = 0; i < 4; i++)
#pragma unroll
                for (int j = 0; j < 4; j++) sacc[i][j] = fmaf(qa[i], kb[j], sacc[i][j]);
        }
#pragma unroll
        for (int i = 0; i < 4; i++) {
            int r = ty * 4 + i;
#pragma unroll
            for (int j = 0; j < 4; j++) {
                int c = tx * 4 + j;
                float val = sacc[i][j] * 0.125f;
                if (s0k + c > s0q + r) val = -1e30f;
                Ss[r * 65 + c] = val;
            }
        }
        __syncthreads();

        if (tid < 64) {
            int r = tid;
            float mo = m_sh[r];
            float mx = mo;
#pragma unroll 8
            for (int c = 0; c < 64; c++) mx = fmaxf(mx, Ss[r * 65 + c]);
            float al = __expf(mo - mx);
            float sum = 0.0f;
#pragma unroll 8
            for (int c = 0; c < 64; c++) {
                float p = __expf(Ss[r * 65 + c] - mx);
                Ss[r * 65 + c] = p;
                sum += p;
            }
            l_sh[r] = l_sh[r] * al + sum;
            m_sh[r] = mx;
            al_sh[r] = al;
        }
        __syncthreads();

        float al[4];
#pragma unroll
        for (int i = 0; i < 4; i++) al[i] = al_sh[ty * 4 + i];
#pragma unroll
        for (int i = 0; i < 4; i++)
#pragma unroll
            for (int j = 0; j < 4; j++) oacc[i][j] *= al[i];

#pragma unroll 8
        for (int kk = 0; kk < 64; kk++) {
            float pa[4], vb[4];
#pragma unroll
            for (int i = 0; i < 4; i++) pa[i] = Ss[(ty * 4 + i) * 65 + kk];
#pragma unroll
            for (int j = 0; j < 4; j++) vb[j] = Vs[kk * 65 + tx * 4 + j];
#pragma unroll
            for (int i = 0; i < 4; i++)
#pragma unroll
                for (int j = 0; j < 4; j++) oacc[i][j] = fmaf(pa[i], vb[j], oacc[i][j]);
        }
    }

#pragma unroll
    for (int i = 0; i < 4; i++) {
        int r = ty * 4 + i;
        float inv_l = 1.0f / l_sh[r];
#pragma unroll
        for (int j = 0; j < 4; j++) {
            int d = tx * 4 + j;
            o[(size_t)(b * SS + s0q + r) * (HH * DKK) + h * DKK + d] = oacc[i][j] * inv_l;
        }
    }
}

// ---------------------------------------------------------------------------
// Launch
// ---------------------------------------------------------------------------
extern "C" void kernel_launch(void* const* d_in, const int* in_sizes, int n_in,
                              void* d_out, int out_size) {
    const float* x  = (const float*)d_in[0];
    const float* Wq = (const float*)d_in[2];
    const float* bq = (const float*)d_in[3];
    const float* Wk = (const float*)d_in[4];
    const float* bk = (const float*)d_in[5];
    const float* Wv = (const float*)d_in[6];
    const float* bv = (const float*)d_in[7];
    const float* Wo = (const float*)d_in[8];
    const float* bo = (const float*)d_in[9];
    float* out = (float*)d_out;

    float *gqkv, *go, *gc, *gs, *gbqkv;
    cudaGetSymbolAddress((void**)&gqkv, g_qkv);
    cudaGetSymbolAddress((void**)&go, g_o);
    cudaGetSymbolAddress((void**)&gc, g_cos);
    cudaGetSymbolAddress((void**)&gs, g_sin);
    cudaGetSymbolAddress((void**)&gbqkv, g_bqkv);

    __nv_bfloat16 *xhi, *xlo, *ohi, *olo, *wqkvhi, *wqkvlo, *wohi, *wolo;
    cudaGetSymbolAddress((void**)&xhi, g_xhi);
    cudaGetSymbolAddress((void**)&xlo, g_xlo);
    cudaGetSymbolAddress((void**)&ohi, g_ohi);
    cudaGetSymbolAddress((void**)&olo, g_olo);
    cudaGetSymbolAddress((void**)&wqkvhi, g_wqkvhi);
    cudaGetSymbolAddress((void**)&wqkvlo, g_wqkvlo);
    cudaGetSymbolAddress((void**)&wohi, g_wohi);
    cudaGetSymbolAddress((void**)&wolo, g_wolo);

    const int M = BB * SS;  // 4096
    dim3 blk(256);

    rope_table_kernel<<<(SS * 32 + 255) / 256, 256>>>(gc, gs);

    int nx = M * DD;
    split_kernel<<<(nx + 255) / 256, 256>>>(x, xhi, xlo, nx);
    pack_wqkv_kernel<<<(DD * NQKV + 255) / 256, 256>>>(Wq, Wk, Wv, bq, bk, bv,
                                                       wqkvhi, wqkvlo, gbqkv);
    split_kernel<<<(DD * DD + 255) / 256, 256>>>(Wo, wohi, wolo, DD * DD);

    cudaFuncSetAttribute(gemm_bf16x3_v2, cudaFuncAttributeMaxDynamicSharedMemorySize,
                         GSM_TOTAL);

    // QKV = x @ Wqkv + bqkv (one launch, 12x32 = 384 blocks)
    gemm_bf16x3_v2<<<dim3(NQKV / 128, M / 128), blk, GSM_TOTAL>>>(
        xhi, xlo, wqkvhi, wqkvlo, gbqkv, gqkv, M, NQKV, 1024);

    int nrope = BB * SS * (HH + KHH) * 32;
    rope_apply_kernel<<<(nrope + 255) / 256, 256>>>(gqkv, gc, gs);

    size_t flash_smem = FLASH_SMEM_FLOATS * sizeof(float);
    cudaFuncSetAttribute(flash_kernel, cudaFuncAttributeMaxDynamicSharedMemorySize,
                         (int)flash_smem);
    flash_kernel<<<dim3(SS / 64, HH, BB), blk, flash_smem>>>(gqkv, go);

    split_kernel<<<(nx + 255) / 256, 256>>>(go, ohi, olo, nx);
    gemm_bf16x3_v2<<<dim3(1024 / 128, M / 128), blk, GSM_TOTAL>>>(
        ohi, olo, wohi, wolo, bo, out, M, 1024, 1024);
}